// round 16
// baseline (speedup 1.0000x reference)
#include <cuda_runtime.h>
#include <math.h>

#define DD 1024
#define FF 4096
#define SS 1024
#define TT 2048          // total tokens B*S
#define HH 16
#define HD 64
#define NL 3
#define NE 8
#define VV 32000

// ---------------- scratch (static device globals; no runtime allocs) ----------------
__device__ float g_x  [TT * DD];
__device__ float g_q  [TT * DD];
__device__ float g_k  [TT * DD];
__device__ float g_v  [TT * DD];
__device__ float g_ao [TT * DD];
__device__ float g_t  [TT * DD];
__device__ float g_ff [TT * FF];
__device__ float g_eh [2 * TT * FF];   // expert hidden, row = slot (2*t + kk)
__device__ float g_sel[2 * TT * DD];   // expert output, row = slot
__device__ float g_w2 [2 * TT];
__device__ int   g_tok [NE * TT];
__device__ int   g_slot[NE * TT];
__device__ int   g_cnt [NE];
__device__ float g_xln[TT * DD];

// ---------------- packed f32x2 helpers ----------------
__device__ __forceinline__ unsigned long long pack2(float x, float y) {
    unsigned long long r;
    asm("mov.b64 %0, {%1, %2};" : "=l"(r) : "r"(__float_as_uint(x)), "r"(__float_as_uint(y)));
    return r;
}
__device__ __forceinline__ float2 unpack2(unsigned long long v) {
    unsigned int lo, hi;
    asm("mov.b64 {%0, %1}, %2;" : "=r"(lo), "=r"(hi) : "l"(v));
    float2 r; r.x = __uint_as_float(lo); r.y = __uint_as_float(hi); return r;
}
#define FMA2(c, a, b) asm("fma.rn.f32x2 %0, %1, %2, %0;" : "+l"(c) : "l"(a), "l"(b))

// ---------------- generic fp32 GEMM ----------------
// C[cIdx[m]] = op( gather(A,aIdx)[m] @ B_z + bias_z ), 128x128 tile, K%16==0, N%128==0.
// z = blockIdx.z selects expert slice of B/bias/index lists. cnt limits rows.
__global__ void __launch_bounds__(256) gemm_k(
    const float* __restrict__ A, int lda,
    const float* __restrict__ Bm, int ldb, long bz,
    const float* __restrict__ bias, long biasz,
    float* __restrict__ C, int ldc,
    int M, int N, int K,
    const int* __restrict__ aIdx, const int* __restrict__ cIdx, int idxz,
    const int* __restrict__ cnt, int relu)
{
    __shared__ float As[2][16][132];
    __shared__ float Bs[2][16][128];

    int z = blockIdx.z;
    int Meff = cnt ? cnt[z] : M;
    int row0 = blockIdx.y * 128;
    if (row0 >= Meff) return;
    int col0 = blockIdx.x * 128;

    const float* B  = Bm + (long)z * bz;
    const float* bv = bias ? bias + (long)z * biasz : 0;
    const int*   aI = aIdx ? aIdx + (long)z * idxz : 0;
    const int*   cI = cIdx ? cIdx + (long)z * idxz : 0;

    int tid = threadIdx.x;
    int am = tid >> 2;                 // 0..63
    int ak = (tid & 3) * 4;            // 0,4,8,12
    int mg0 = row0 + am, mg1 = row0 + am + 64;
    int r0 = (mg0 < Meff) ? (aI ? aI[mg0] : mg0) : 0;
    int r1 = (mg1 < Meff) ? (aI ? aI[mg1] : mg1) : 0;
    const float* aP0 = A + (long)r0 * lda + ak;
    const float* aP1 = A + (long)r1 * lda + ak;

    int bk = tid >> 5;                 // 0..7 (+8)
    int bn = (tid & 31) * 4;
    const float* bP = B + (long)bk * ldb + col0 + bn;

    int m0 = (tid >> 4) * 8;
    int n0 = (tid & 15) * 8;

    unsigned long long acc[8][4];
#pragma unroll
    for (int i = 0; i < 8; i++)
#pragma unroll
        for (int j = 0; j < 4; j++) acc[i][j] = 0ULL;

    int nk = K >> 4;

    float4 ra0 = *(const float4*)aP0;
    float4 ra1 = *(const float4*)aP1;
    float4 rb0 = *(const float4*)bP;
    float4 rb1 = *(const float4*)(bP + 8 * (long)ldb);

    As[0][ak + 0][am] = ra0.x; As[0][ak + 1][am] = ra0.y;
    As[0][ak + 2][am] = ra0.z; As[0][ak + 3][am] = ra0.w;
    As[0][ak + 0][am + 64] = ra1.x; As[0][ak + 1][am + 64] = ra1.y;
    As[0][ak + 2][am + 64] = ra1.z; As[0][ak + 3][am + 64] = ra1.w;
    *(float4*)&Bs[0][bk][bn]     = rb0;
    *(float4*)&Bs[0][bk + 8][bn] = rb1;
    __syncthreads();

    for (int kt = 0; kt < nk; kt++) {
        int cur = kt & 1;
        if (kt + 1 < nk) {
            ra0 = *(const float4*)(aP0 + (long)(kt + 1) * 16);
            ra1 = *(const float4*)(aP1 + (long)(kt + 1) * 16);
            const float* bp = bP + (long)(kt + 1) * 16 * ldb;
            rb0 = *(const float4*)bp;
            rb1 = *(const float4*)(bp + 8 * (long)ldb);
        }
#pragma unroll
        for (int kk = 0; kk < 16; kk++) {
            float4 a0 = *(const float4*)&As[cur][kk][m0];
            float4 a1 = *(const float4*)&As[cur][kk][m0 + 4];
            float4 b0 = *(const float4*)&Bs[cur][kk][n0];
            float4 b1 = *(const float4*)&Bs[cur][kk][n0 + 4];
            unsigned long long bb0 = pack2(b0.x, b0.y);
            unsigned long long bb1 = pack2(b0.z, b0.w);
            unsigned long long bb2 = pack2(b1.x, b1.y);
            unsigned long long bb3 = pack2(b1.z, b1.w);
            float av[8] = {a0.x, a0.y, a0.z, a0.w, a1.x, a1.y, a1.z, a1.w};
#pragma unroll
            for (int i = 0; i < 8; i++) {
                unsigned long long aa = pack2(av[i], av[i]);
                FMA2(acc[i][0], aa, bb0);
                FMA2(acc[i][1], aa, bb1);
                FMA2(acc[i][2], aa, bb2);
                FMA2(acc[i][3], aa, bb3);
            }
        }
        if (kt + 1 < nk) {
            int nxt = cur ^ 1;
            As[nxt][ak + 0][am] = ra0.x; As[nxt][ak + 1][am] = ra0.y;
            As[nxt][ak + 2][am] = ra0.z; As[nxt][ak + 3][am] = ra0.w;
            As[nxt][ak + 0][am + 64] = ra1.x; As[nxt][ak + 1][am + 64] = ra1.y;
            As[nxt][ak + 2][am + 64] = ra1.z; As[nxt][ak + 3][am + 64] = ra1.w;
            *(float4*)&Bs[nxt][bk][bn]     = rb0;
            *(float4*)&Bs[nxt][bk + 8][bn] = rb1;
        }
        __syncthreads();
    }

    float breg[8];
#pragma unroll
    for (int j = 0; j < 8; j++) breg[j] = bv ? bv[col0 + n0 + j] : 0.f;

#pragma unroll
    for (int i = 0; i < 8; i++) {
        int mg = row0 + m0 + i;
        if (mg < Meff) {
            int cr = cI ? cI[mg] : mg;
            float o[8];
#pragma unroll
            for (int j = 0; j < 4; j++) {
                float2 p = unpack2(acc[i][j]);
                o[2 * j]     = p.x + breg[2 * j];
                o[2 * j + 1] = p.y + breg[2 * j + 1];
            }
            if (relu) {
#pragma unroll
                for (int j = 0; j < 8; j++) o[j] = fmaxf(o[j], 0.f);
            }
            float* cp = C + (long)cr * ldc + col0 + n0;
            *(float4*)cp       = make_float4(o[0], o[1], o[2], o[3]);
            *(float4*)(cp + 4) = make_float4(o[4], o[5], o[6], o[7]);
        }
    }
}

// ---------------- embedding + positional encoding ----------------
__global__ void __launch_bounds__(256) embed_k(const int* __restrict__ src,
                                               const float* __restrict__ emb,
                                               float* __restrict__ x)
{
    int t = blockIdx.x, tid = threadIdx.x;
    int c = tid * 4;
    int s = t & (SS - 1);
    float pos = (float)s;
    int v = src[t];
    const float* ep = emb + (long)v * DD + c;
    float4 e = *(const float4*)ep;
    const float kln = -logf(10000.0f) / (float)DD;  // * (2i)
    float o[4] = {e.x, e.y, e.z, e.w};
#pragma unroll
    for (int j = 0; j < 4; j++) {
        int col = c + j;
        int i2 = (col >> 1) * 2;
        float ang = pos * expf(kln * (float)i2);
        float pe = (col & 1) ? cosf(ang) : sinf(ang);
        o[j] = o[j] * 32.0f + pe;                    // sqrt(D)=32
    }
    *(float4*)(x + (long)t * DD + c) = make_float4(o[0], o[1], o[2], o[3]);
}

// ---------------- flash attention: 32 queries/block, hd=64, full attention ----------------
__global__ void __launch_bounds__(256) attn_k(
    const float* __restrict__ q, const float* __restrict__ k,
    const float* __restrict__ v, float* __restrict__ ao)
{
    __shared__ float Qs[32][68];
    __shared__ float KV[64][68];
    __shared__ float Pt[64][33];
    __shared__ float alpha_s[32];

    int b = blockIdx.z, h = blockIdx.y, q0 = blockIdx.x * 32;
    int tid = threadIdx.x;
    int r = tid & 31, g = tid >> 5;

    {   // load Q tile 32x64
        int qr = tid >> 3, qc = (tid & 7) * 8;
        const float* qp = q + ((long)(b * SS + q0 + qr)) * DD + h * HD + qc;
        *(float4*)&Qs[qr][qc]     = *(const float4*)qp;
        *(float4*)&Qs[qr][qc + 4] = *(const float4*)(qp + 4);
    }

    float o[8];
#pragma unroll
    for (int i = 0; i < 8; i++) o[i] = 0.f;
    float mi = -1e30f, li = 0.f;

    int kr = tid >> 2, kc4 = (tid & 3) * 16;

    for (int kt = 0; kt < SS / 64; kt++) {
        {   // load K tile 64x64
            const float* kp = k + ((long)(b * SS + kt * 64 + kr)) * DD + h * HD + kc4;
            *(float4*)&KV[kr][kc4]      = *(const float4*)kp;
            *(float4*)&KV[kr][kc4 + 4]  = *(const float4*)(kp + 4);
            *(float4*)&KV[kr][kc4 + 8]  = *(const float4*)(kp + 8);
            *(float4*)&KV[kr][kc4 + 12] = *(const float4*)(kp + 12);
        }
        __syncthreads();
        {   // scores: thread (r,g) -> query r, k-cols g*8..g*8+7
            float sreg[8];
#pragma unroll
            for (int j = 0; j < 8; j++) sreg[j] = 0.f;
#pragma unroll
            for (int d0 = 0; d0 < 64; d0 += 4) {
                float4 qv = *(const float4*)&Qs[r][d0];
#pragma unroll
                for (int j = 0; j < 8; j++) {
                    float4 kv = *(const float4*)&KV[g * 8 + j][d0];
                    sreg[j] += qv.x * kv.x + qv.y * kv.y + qv.z * kv.z + qv.w * kv.w;
                }
            }
#pragma unroll
            for (int j = 0; j < 8; j++) Pt[g * 8 + j][r] = sreg[j] * 0.125f;
        }
        __syncthreads();
        {   // load V tile into same buffer (K no longer needed)
            const float* vp = v + ((long)(b * SS + kt * 64 + kr)) * DD + h * HD + kc4;
            *(float4*)&KV[kr][kc4]      = *(const float4*)vp;
            *(float4*)&KV[kr][kc4 + 4]  = *(const float4*)(vp + 4);
            *(float4*)&KV[kr][kc4 + 8]  = *(const float4*)(vp + 8);
            *(float4*)&KV[kr][kc4 + 12] = *(const float4*)(vp + 12);
        }
        if (tid < 32) {  // online softmax for query row tid
            float tm = -1e30f;
            for (int j = 0; j < 64; j++) tm = fmaxf(tm, Pt[j][tid]);
            float nm = fmaxf(mi, tm);
            float al = __expf(mi - nm);
            float ls = 0.f;
            for (int j = 0; j < 64; j++) {
                float e = __expf(Pt[j][tid] - nm);
                Pt[j][tid] = e;
                ls += e;
            }
            li = li * al + ls;
            mi = nm;
            alpha_s[tid] = al;
        }
        __syncthreads();
        {   // O = O*alpha + P @ V ; thread handles dims g*8..g*8+7 of query r
            float al = alpha_s[r];
#pragma unroll
            for (int i = 0; i < 8; i++) o[i] *= al;
            for (int kc = 0; kc < 64; kc++) {
                float p = Pt[kc][r];
                float4 v0 = *(const float4*)&KV[kc][g * 8];
                float4 v1 = *(const float4*)&KV[kc][g * 8 + 4];
                o[0] += p * v0.x; o[1] += p * v0.y; o[2] += p * v0.z; o[3] += p * v0.w;
                o[4] += p * v1.x; o[5] += p * v1.y; o[6] += p * v1.z; o[7] += p * v1.w;
            }
        }
        __syncthreads();
    }
    if (tid < 32) alpha_s[tid] = 1.f / li;
    __syncthreads();
    {
        float inv = alpha_s[r];
        float* op = ao + ((long)(b * SS + q0 + r)) * DD + h * HD + g * 8;
        *(float4*)op       = make_float4(o[0] * inv, o[1] * inv, o[2] * inv, o[3] * inv);
        *(float4*)(op + 4) = make_float4(o[4] * inv, o[5] * inv, o[6] * inv, o[7] * inv);
    }
}

// ---------------- layernorm over D=1024 (block per row) ----------------
__device__ __forceinline__ void ln_body(float4 vv, const float* __restrict__ gg,
                                        const float* __restrict__ bb,
                                        float* __restrict__ out, int t, int tid)
{
    __shared__ float red[2][8];
    __shared__ float stat[2];
    float s  = vv.x + vv.y + vv.z + vv.w;
    float qq = vv.x * vv.x + vv.y * vv.y + vv.z * vv.z + vv.w * vv.w;
#pragma unroll
    for (int off = 16; off; off >>= 1) {
        s  += __shfl_down_sync(0xffffffffu, s, off);
        qq += __shfl_down_sync(0xffffffffu, qq, off);
    }
    if ((tid & 31) == 0) { red[0][tid >> 5] = s; red[1][tid >> 5] = qq; }
    __syncthreads();
    if (tid == 0) {
        float ts = 0.f, tq = 0.f;
        for (int i = 0; i < 8; i++) { ts += red[0][i]; tq += red[1][i]; }
        float mu  = ts * (1.f / DD);
        float var = tq * (1.f / DD) - mu * mu;
        stat[0] = mu; stat[1] = rsqrtf(var + 1e-5f);
    }
    __syncthreads();
    float mu = stat[0], rs = stat[1];
    float4 gv  = ((const float4*)gg)[tid];
    float4 bvv = ((const float4*)bb)[tid];
    float4 ov;
    ov.x = (vv.x - mu) * rs * gv.x + bvv.x;
    ov.y = (vv.y - mu) * rs * gv.y + bvv.y;
    ov.z = (vv.z - mu) * rs * gv.z + bvv.z;
    ov.w = (vv.w - mu) * rs * gv.w + bvv.w;
    ((float4*)(out + (long)t * DD))[tid] = ov;
}

__global__ void __launch_bounds__(256) ln_k(const float* __restrict__ x,
                                            const float* __restrict__ res,
                                            const float* __restrict__ gg,
                                            const float* __restrict__ bb,
                                            float* __restrict__ out)
{
    int t = blockIdx.x, tid = threadIdx.x;
    float4 vv = ((const float4*)(x + (long)t * DD))[tid];
    if (res) {
        float4 rr = ((const float4*)(res + (long)t * DD))[tid];
        vv.x += rr.x; vv.y += rr.y; vv.z += rr.z; vv.w += rr.w;
    }
    ln_body(vv, gg, bb, out, t, tid);
}

// ---------------- MoE combine + final LN ----------------
__global__ void __launch_bounds__(256) comb_ln_k(const float* __restrict__ sel,
                                                 const float* __restrict__ w2,
                                                 const float* __restrict__ gg,
                                                 const float* __restrict__ bb,
                                                 float* __restrict__ out)
{
    int t = blockIdx.x, tid = threadIdx.x;
    float w0 = w2[2 * t], w1 = w2[2 * t + 1];
    float4 va = ((const float4*)(sel + (long)(2 * t) * DD))[tid];
    float4 vb = ((const float4*)(sel + (long)(2 * t + 1) * DD))[tid];
    float4 vv;
    vv.x = w0 * va.x + w1 * vb.x;
    vv.y = w0 * va.y + w1 * vb.y;
    vv.z = w0 * va.z + w1 * vb.z;
    vv.w = w0 * va.w + w1 * vb.w;
    ln_body(vv, gg, bb, out, t, tid);
}

// ---------------- gate: logits, top-2 (jax tie semantics), softmax, routing ----------------
__global__ void zero_cnt_k(int* __restrict__ cnt) {
    if (threadIdx.x < NE) cnt[threadIdx.x] = 0;
}

__global__ void __launch_bounds__(256) gate_k(const float* __restrict__ x,
                                              const float* __restrict__ gW,
                                              const float* __restrict__ gb,
                                              float* __restrict__ w2,
                                              int* __restrict__ tok,
                                              int* __restrict__ slot,
                                              int* __restrict__ cnt)
{
    __shared__ float xs[DD];
    __shared__ float lg[NE];
    int t = blockIdx.x, tid = threadIdx.x;
    ((float4*)xs)[tid] = ((const float4*)(x + (long)t * DD))[tid];
    __syncthreads();
    int w = tid >> 5, lane = tid & 31;
    float s = 0.f;
    for (int d = lane; d < DD; d += 32) s += xs[d] * gW[(long)d * NE + w];
#pragma unroll
    for (int off = 16; off; off >>= 1) s += __shfl_down_sync(0xffffffffu, s, off);
    if (lane == 0) lg[w] = s + gb[w];
    __syncthreads();
    if (tid == 0) {
        float b1v = -1e30f; int i1 = 0;
        for (int e = 0; e < NE; e++) if (lg[e] > b1v) { b1v = lg[e]; i1 = e; }
        float b2v = -1e30f; int i2 = 0;
        for (int e = 0; e < NE; e++) if (e != i1 && lg[e] > b2v) { b2v = lg[e]; i2 = e; }
        float m = fmaxf(b1v, b2v);
        float e0 = expf(b1v - m), e1 = expf(b2v - m);
        float inv = 1.f / (e0 + e1);
        w2[2 * t]     = e0 * inv;
        w2[2 * t + 1] = e1 * inv;
        int p0 = atomicAdd(&cnt[i1], 1);
        tok[i1 * TT + p0] = t; slot[i1 * TT + p0] = 2 * t;
        int p1 = atomicAdd(&cnt[i2], 1);
        tok[i2 * TT + p1] = t; slot[i2 * TT + p1] = 2 * t + 1;
    }
}

// ---------------- host orchestration ----------------
extern "C" void kernel_launch(void* const* d_in, const int* in_sizes, int n_in,
                              void* d_out, int out_size) {
    const int*   src    = (const int*)  d_in[0];
    const float* emb    = (const float*)d_in[1];
    const float* Wq     = (const float*)d_in[2];
    const float* bq     = (const float*)d_in[3];
    const float* Wk     = (const float*)d_in[4];
    const float* bk     = (const float*)d_in[5];
    const float* Wv     = (const float*)d_in[6];
    const float* bv     = (const float*)d_in[7];
    const float* Wo     = (const float*)d_in[8];
    const float* bo     = (const float*)d_in[9];
    const float* ln1_g  = (const float*)d_in[10];
    const float* ln1_b  = (const float*)d_in[11];
    const float* W1     = (const float*)d_in[12];
    const float* b1     = (const float*)d_in[13];
    const float* W2     = (const float*)d_in[14];
    const float* b2     = (const float*)d_in[15];
    const float* ln2_g  = (const float*)d_in[16];
    const float* ln2_b  = (const float*)d_in[17];
    const float* gate_W = (const float*)d_in[18];
    const float* gate_b = (const float*)d_in[19];
    const float* eW1    = (const float*)d_in[20];
    const float* eb1    = (const float*)d_in[21];
    const float* eW2    = (const float*)d_in[22];
    const float* eb2    = (const float*)d_in[23];
    const float* fln_g  = (const float*)d_in[24];
    const float* fln_b  = (const float*)d_in[25];
    const float* out_W  = (const float*)d_in[26];
    const float* out_b  = (const float*)d_in[27];
    float* outp = (float*)d_out;

    float *p_x, *p_q, *p_k, *p_v, *p_ao, *p_t, *p_ff, *p_eh, *p_sel, *p_w2, *p_xln;
    int *p_tok, *p_slot, *p_cnt;
    cudaGetSymbolAddress((void**)&p_x,   g_x);
    cudaGetSymbolAddress((void**)&p_q,   g_q);
    cudaGetSymbolAddress((void**)&p_k,   g_k);
    cudaGetSymbolAddress((void**)&p_v,   g_v);
    cudaGetSymbolAddress((void**)&p_ao,  g_ao);
    cudaGetSymbolAddress((void**)&p_t,   g_t);
    cudaGetSymbolAddress((void**)&p_ff,  g_ff);
    cudaGetSymbolAddress((void**)&p_eh,  g_eh);
    cudaGetSymbolAddress((void**)&p_sel, g_sel);
    cudaGetSymbolAddress((void**)&p_w2,  g_w2);
    cudaGetSymbolAddress((void**)&p_xln, g_xln);
    cudaGetSymbolAddress((void**)&p_tok, g_tok);
    cudaGetSymbolAddress((void**)&p_slot,g_slot);
    cudaGetSymbolAddress((void**)&p_cnt, g_cnt);

    dim3 blk(256);

    embed_k<<<TT, blk>>>(src, emb, p_x);

    for (int l = 0; l < NL; l++) {
        const float* wq = Wq + (long)l * DD * DD;
        const float* wk = Wk + (long)l * DD * DD;
        const float* wv = Wv + (long)l * DD * DD;
        const float* wo = Wo + (long)l * DD * DD;
        const float* w1 = W1 + (long)l * DD * FF;
        const float* w2m = W2 + (long)l * FF * DD;

        dim3 gD(DD / 128, TT / 128, 1);   // N=1024
        dim3 gF(FF / 128, TT / 128, 1);   // N=4096

        gemm_k<<<gD, blk>>>(p_x, DD, wq, DD, 0, bq + (long)l * DD, 0, p_q, DD,
                            TT, DD, DD, 0, 0, 0, 0, 0);
        gemm_k<<<gD, blk>>>(p_x, DD, wk, DD, 0, bk + (long)l * DD, 0, p_k, DD,
                            TT, DD, DD, 0, 0, 0, 0, 0);
        gemm_k<<<gD, blk>>>(p_x, DD, wv, DD, 0, bv + (long)l * DD, 0, p_v, DD,
                            TT, DD, DD, 0, 0, 0, 0, 0);

        attn_k<<<dim3(SS / 32, HH, 2), blk>>>(p_q, p_k, p_v, p_ao);

        gemm_k<<<gD, blk>>>(p_ao, DD, wo, DD, 0, bo + (long)l * DD, 0, p_t, DD,
                            TT, DD, DD, 0, 0, 0, 0, 0);

        ln_k<<<TT, blk>>>(p_t, p_x, ln1_g + (long)l * DD, ln1_b + (long)l * DD, p_x);

        gemm_k<<<gF, blk>>>(p_x, DD, w1, FF, 0, b1 + (long)l * FF, 0, p_ff, FF,
                            TT, FF, DD, 0, 0, 0, 0, 1);
        gemm_k<<<gD, blk>>>(p_ff, FF, w2m, DD, 0, b2 + (long)l * DD, 0, p_t, DD,
                            TT, DD, FF, 0, 0, 0, 0, 0);

        ln_k<<<TT, blk>>>(p_t, p_x, ln2_g + (long)l * DD, ln2_b + (long)l * DD, p_x);
    }

    // ---- MoE ----
    zero_cnt_k<<<1, 32>>>(p_cnt);
    gate_k<<<TT, blk>>>(p_x, gate_W, gate_b, p_w2, p_tok, p_slot, p_cnt);

    // expert FFN1: h = relu(gather(x) @ eW1[e] + eb1[e]) -> g_eh (rows = slots)
    gemm_k<<<dim3(FF / 128, TT / 128, NE), blk>>>(
        p_x, DD, eW1, FF, (long)DD * FF, eb1, FF, p_eh, FF,
        TT, FF, DD, p_tok, p_slot, TT, p_cnt, 1);
    // expert FFN2: y = gather(h) @ eW2[e] + eb2[e] -> g_sel (rows = slots)
    gemm_k<<<dim3(DD / 128, TT / 128, NE), blk>>>(
        p_eh, FF, eW2, DD, (long)FF * DD, eb2, DD, p_sel, DD,
        TT, DD, FF, p_slot, p_slot, TT, p_cnt, 0);

    comb_ln_k<<<TT, blk>>>(p_sel, p_w2, fln_g, fln_b, p_xln);

    // output projection: [2048,1024] @ [1024,32000]
    gemm_k<<<dim3(VV / 128, TT / 128, 1), blk>>>(
        p_xln, DD, out_W, VV, 0, out_b, 0, outp, VV,
        TT, VV, DD, 0, 0, 0, 0, 0);
}

// round 17
// speedup vs baseline: 1.0004x; 1.0004x over previous
#include <cuda_runtime.h>
#include <math.h>

#define DD 1024
#define FF 4096
#define SS 1024
#define TT 2048          // total tokens B*S
#define HH 16
#define HD 64
#define NL 3
#define NE 8
#define VV 32000

// ---------------- scratch (static device globals; no runtime allocs) ----------------
__device__ float g_x  [TT * DD];
__device__ float g_q  [TT * DD];
__device__ float g_k  [TT * DD];
__device__ float g_v  [TT * DD];
__device__ float g_ao [TT * DD];
__device__ float g_t  [TT * DD];
__device__ float g_ff [TT * FF];
__device__ float g_eh [2 * TT * FF];   // expert hidden, row = slot (2*t + kk)
__device__ float g_sel[2 * TT * DD];   // expert output, row = slot
__device__ float g_w2 [2 * TT];
__device__ int   g_tok [NE * TT];
__device__ int   g_slot[NE * TT];
__device__ int   g_cnt [NE];
__device__ float g_xln[TT * DD];

// ---------------- packed f32x2 helpers ----------------
__device__ __forceinline__ unsigned long long pack2(float x, float y) {
    unsigned long long r;
    asm("mov.b64 %0, {%1, %2};" : "=l"(r) : "r"(__float_as_uint(x)), "r"(__float_as_uint(y)));
    return r;
}
__device__ __forceinline__ float2 unpack2(unsigned long long v) {
    unsigned int lo, hi;
    asm("mov.b64 {%0, %1}, %2;" : "=r"(lo), "=r"(hi) : "l"(v));
    float2 r; r.x = __uint_as_float(lo); r.y = __uint_as_float(hi); return r;
}
#define FMA2(c, a, b) asm("fma.rn.f32x2 %0, %1, %2, %0;" : "+l"(c) : "l"(a), "l"(b))

// ---------------- generic fp32 GEMM ----------------
// C[cIdx[m]] = op( gather(A,aIdx)[m] @ B_z + bias_z ), 128x128 tile, K%16==0, N%128==0.
// z = blockIdx.z selects expert slice of B/bias/index lists. cnt limits rows.
__global__ void __launch_bounds__(256) gemm_k(
    const float* __restrict__ A, int lda,
    const float* __restrict__ Bm, int ldb, long bz,
    const float* __restrict__ bias, long biasz,
    float* __restrict__ C, int ldc,
    int M, int N, int K,
    const int* __restrict__ aIdx, const int* __restrict__ cIdx, int idxz,
    const int* __restrict__ cnt, int relu)
{
    __shared__ float As[2][16][132];
    __shared__ float Bs[2][16][128];

    int z = blockIdx.z;
    int Meff = cnt ? cnt[z] : M;
    int row0 = blockIdx.y * 128;
    if (row0 >= Meff) return;
    int col0 = blockIdx.x * 128;

    const float* B  = Bm + (long)z * bz;
    const float* bv = bias ? bias + (long)z * biasz : 0;
    const int*   aI = aIdx ? aIdx + (long)z * idxz : 0;
    const int*   cI = cIdx ? cIdx + (long)z * idxz : 0;

    int tid = threadIdx.x;
    int am = tid >> 2;                 // 0..63
    int ak = (tid & 3) * 4;            // 0,4,8,12
    int mg0 = row0 + am, mg1 = row0 + am + 64;
    int r0 = (mg0 < Meff) ? (aI ? aI[mg0] : mg0) : 0;
    int r1 = (mg1 < Meff) ? (aI ? aI[mg1] : mg1) : 0;
    const float* aP0 = A + (long)r0 * lda + ak;
    const float* aP1 = A + (long)r1 * lda + ak;

    int bk = tid >> 5;                 // 0..7 (+8)
    int bn = (tid & 31) * 4;
    const float* bP = B + (long)bk * ldb + col0 + bn;

    int m0 = (tid >> 4) * 8;
    int n0 = (tid & 15) * 8;

    unsigned long long acc[8][4];
#pragma unroll
    for (int i = 0; i < 8; i++)
#pragma unroll
        for (int j = 0; j < 4; j++) acc[i][j] = 0ULL;

    int nk = K >> 4;

    float4 ra0 = *(const float4*)aP0;
    float4 ra1 = *(const float4*)aP1;
    float4 rb0 = *(const float4*)bP;
    float4 rb1 = *(const float4*)(bP + 8 * (long)ldb);

    As[0][ak + 0][am] = ra0.x; As[0][ak + 1][am] = ra0.y;
    As[0][ak + 2][am] = ra0.z; As[0][ak + 3][am] = ra0.w;
    As[0][ak + 0][am + 64] = ra1.x; As[0][ak + 1][am + 64] = ra1.y;
    As[0][ak + 2][am + 64] = ra1.z; As[0][ak + 3][am + 64] = ra1.w;
    *(float4*)&Bs[0][bk][bn]     = rb0;
    *(float4*)&Bs[0][bk + 8][bn] = rb1;
    __syncthreads();

    for (int kt = 0; kt < nk; kt++) {
        int cur = kt & 1;
        if (kt + 1 < nk) {
            ra0 = *(const float4*)(aP0 + (long)(kt + 1) * 16);
            ra1 = *(const float4*)(aP1 + (long)(kt + 1) * 16);
            const float* bp = bP + (long)(kt + 1) * 16 * ldb;
            rb0 = *(const float4*)bp;
            rb1 = *(const float4*)(bp + 8 * (long)ldb);
        }
#pragma unroll
        for (int kk = 0; kk < 16; kk++) {
            float4 a0 = *(const float4*)&As[cur][kk][m0];
            float4 a1 = *(const float4*)&As[cur][kk][m0 + 4];
            float4 b0 = *(const float4*)&Bs[cur][kk][n0];
            float4 b1 = *(const float4*)&Bs[cur][kk][n0 + 4];
            unsigned long long bb0 = pack2(b0.x, b0.y);
            unsigned long long bb1 = pack2(b0.z, b0.w);
            unsigned long long bb2 = pack2(b1.x, b1.y);
            unsigned long long bb3 = pack2(b1.z, b1.w);
            float av[8] = {a0.x, a0.y, a0.z, a0.w, a1.x, a1.y, a1.z, a1.w};
#pragma unroll
            for (int i = 0; i < 8; i++) {
                unsigned long long aa = pack2(av[i], av[i]);
                FMA2(acc[i][0], aa, bb0);
                FMA2(acc[i][1], aa, bb1);
                FMA2(acc[i][2], aa, bb2);
                FMA2(acc[i][3], aa, bb3);
            }
        }
        if (kt + 1 < nk) {
            int nxt = cur ^ 1;
            As[nxt][ak + 0][am] = ra0.x; As[nxt][ak + 1][am] = ra0.y;
            As[nxt][ak + 2][am] = ra0.z; As[nxt][ak + 3][am] = ra0.w;
            As[nxt][ak + 0][am + 64] = ra1.x; As[nxt][ak + 1][am + 64] = ra1.y;
            As[nxt][ak + 2][am + 64] = ra1.z; As[nxt][ak + 3][am + 64] = ra1.w;
            *(float4*)&Bs[nxt][bk][bn]     = rb0;
            *(float4*)&Bs[nxt][bk + 8][bn] = rb1;
        }
        __syncthreads();
    }

    float breg[8];
#pragma unroll
    for (int j = 0; j < 8; j++) breg[j] = bv ? bv[col0 + n0 + j] : 0.f;

#pragma unroll
    for (int i = 0; i < 8; i++) {
        int mg = row0 + m0 + i;
        if (mg < Meff) {
            int cr = cI ? cI[mg] : mg;
            float o[8];
#pragma unroll
            for (int j = 0; j < 4; j++) {
                float2 p = unpack2(acc[i][j]);
                o[2 * j]     = p.x + breg[2 * j];
                o[2 * j + 1] = p.y + breg[2 * j + 1];
            }
            if (relu) {
#pragma unroll
                for (int j = 0; j < 8; j++) o[j] = fmaxf(o[j], 0.f);
            }
            float* cp = C + (long)cr * ldc + col0 + n0;
            *(float4*)cp       = make_float4(o[0], o[1], o[2], o[3]);
            *(float4*)(cp + 4) = make_float4(o[4], o[5], o[6], o[7]);
        }
    }
}

// ---------------- embedding + positional encoding ----------------
__global__ void __launch_bounds__(256) embed_k(const int* __restrict__ src,
                                               const float* __restrict__ emb,
                                               float* __restrict__ x)
{
    int t = blockIdx.x, tid = threadIdx.x;
    int c = tid * 4;
    int s = t & (SS - 1);
    float pos = (float)s;
    int v = src[t];
    const float* ep = emb + (long)v * DD + c;
    float4 e = *(const float4*)ep;
    const float kln = -logf(10000.0f) / (float)DD;  // * (2i)
    float o[4] = {e.x, e.y, e.z, e.w};
#pragma unroll
    for (int j = 0; j < 4; j++) {
        int col = c + j;
        int i2 = (col >> 1) * 2;
        float ang = pos * expf(kln * (float)i2);
        float pe = (col & 1) ? cosf(ang) : sinf(ang);
        o[j] = o[j] * 32.0f + pe;                    // sqrt(D)=32
    }
    *(float4*)(x + (long)t * DD + c) = make_float4(o[0], o[1], o[2], o[3]);
}

// ---------------- flash attention: 32 queries/block, hd=64, full attention ----------------
__global__ void __launch_bounds__(256) attn_k(
    const float* __restrict__ q, const float* __restrict__ k,
    const float* __restrict__ v, float* __restrict__ ao)
{
    __shared__ float Qs[32][68];
    __shared__ float KV[64][68];
    __shared__ float Pt[64][33];
    __shared__ float alpha_s[32];

    int b = blockIdx.z, h = blockIdx.y, q0 = blockIdx.x * 32;
    int tid = threadIdx.x;
    int r = tid & 31, g = tid >> 5;

    {   // load Q tile 32x64
        int qr = tid >> 3, qc = (tid & 7) * 8;
        const float* qp = q + ((long)(b * SS + q0 + qr)) * DD + h * HD + qc;
        *(float4*)&Qs[qr][qc]     = *(const float4*)qp;
        *(float4*)&Qs[qr][qc + 4] = *(const float4*)(qp + 4);
    }

    float o[8];
#pragma unroll
    for (int i = 0; i < 8; i++) o[i] = 0.f;
    float mi = -1e30f, li = 0.f;

    int kr = tid >> 2, kc4 = (tid & 3) * 16;

    for (int kt = 0; kt < SS / 64; kt++) {
        {   // load K tile 64x64
            const float* kp = k + ((long)(b * SS + kt * 64 + kr)) * DD + h * HD + kc4;
            *(float4*)&KV[kr][kc4]      = *(const float4*)kp;
            *(float4*)&KV[kr][kc4 + 4]  = *(const float4*)(kp + 4);
            *(float4*)&KV[kr][kc4 + 8]  = *(const float4*)(kp + 8);
            *(float4*)&KV[kr][kc4 + 12] = *(const float4*)(kp + 12);
        }
        __syncthreads();
        {   // scores: thread (r,g) -> query r, k-cols g*8..g*8+7
            float sreg[8];
#pragma unroll
            for (int j = 0; j < 8; j++) sreg[j] = 0.f;
#pragma unroll
            for (int d0 = 0; d0 < 64; d0 += 4) {
                float4 qv = *(const float4*)&Qs[r][d0];
#pragma unroll
                for (int j = 0; j < 8; j++) {
                    float4 kv = *(const float4*)&KV[g * 8 + j][d0];
                    sreg[j] += qv.x * kv.x + qv.y * kv.y + qv.z * kv.z + qv.w * kv.w;
                }
            }
#pragma unroll
            for (int j = 0; j < 8; j++) Pt[g * 8 + j][r] = sreg[j] * 0.125f;
        }
        __syncthreads();
        {   // load V tile into same buffer (K no longer needed)
            const float* vp = v + ((long)(b * SS + kt * 64 + kr)) * DD + h * HD + kc4;
            *(float4*)&KV[kr][kc4]      = *(const float4*)vp;
            *(float4*)&KV[kr][kc4 + 4]  = *(const float4*)(vp + 4);
            *(float4*)&KV[kr][kc4 + 8]  = *(const float4*)(vp + 8);
            *(float4*)&KV[kr][kc4 + 12] = *(const float4*)(vp + 12);
        }
        if (tid < 32) {  // online softmax for query row tid
            float tm = -1e30f;
            for (int j = 0; j < 64; j++) tm = fmaxf(tm, Pt[j][tid]);
            float nm = fmaxf(mi, tm);
            float al = __expf(mi - nm);
            float ls = 0.f;
            for (int j = 0; j < 64; j++) {
                float e = __expf(Pt[j][tid] - nm);
                Pt[j][tid] = e;
                ls += e;
            }
            li = li * al + ls;
            mi = nm;
            alpha_s[tid] = al;
        }
        __syncthreads();
        {   // O = O*alpha + P @ V ; thread handles dims g*8..g*8+7 of query r
            float al = alpha_s[r];
#pragma unroll
            for (int i = 0; i < 8; i++) o[i] *= al;
            for (int kc = 0; kc < 64; kc++) {
                float p = Pt[kc][r];
                float4 v0 = *(const float4*)&KV[kc][g * 8];
                float4 v1 = *(const float4*)&KV[kc][g * 8 + 4];
                o[0] += p * v0.x; o[1] += p * v0.y; o[2] += p * v0.z; o[3] += p * v0.w;
                o[4] += p * v1.x; o[5] += p * v1.y; o[6] += p * v1.z; o[7] += p * v1.w;
            }
        }
        __syncthreads();
    }
    if (tid < 32) alpha_s[tid] = 1.f / li;
    __syncthreads();
    {
        float inv = alpha_s[r];
        float* op = ao + ((long)(b * SS + q0 + r)) * DD + h * HD + g * 8;
        *(float4*)op       = make_float4(o[0] * inv, o[1] * inv, o[2] * inv, o[3] * inv);
        *(float4*)(op + 4) = make_float4(o[4] * inv, o[5] * inv, o[6] * inv, o[7] * inv);
    }
}

// ---------------- layernorm over D=1024 (block per row) ----------------
__device__ __forceinline__ void ln_body(float4 vv, const float* __restrict__ gg,
                                        const float* __restrict__ bb,
                                        float* __restrict__ out, int t, int tid)
{
    __shared__ float red[2][8];
    __shared__ float stat[2];
    float s  = vv.x + vv.y + vv.z + vv.w;
    float qq = vv.x * vv.x + vv.y * vv.y + vv.z * vv.z + vv.w * vv.w;
#pragma unroll
    for (int off = 16; off; off >>= 1) {
        s  += __shfl_down_sync(0xffffffffu, s, off);
        qq += __shfl_down_sync(0xffffffffu, qq, off);
    }
    if ((tid & 31) == 0) { red[0][tid >> 5] = s; red[1][tid >> 5] = qq; }
    __syncthreads();
    if (tid == 0) {
        float ts = 0.f, tq = 0.f;
        for (int i = 0; i < 8; i++) { ts += red[0][i]; tq += red[1][i]; }
        float mu  = ts * (1.f / DD);
        float var = tq * (1.f / DD) - mu * mu;
        stat[0] = mu; stat[1] = rsqrtf(var + 1e-5f);
    }
    __syncthreads();
    float mu = stat[0], rs = stat[1];
    float4 gv  = ((const float4*)gg)[tid];
    float4 bvv = ((const float4*)bb)[tid];
    float4 ov;
    ov.x = (vv.x - mu) * rs * gv.x + bvv.x;
    ov.y = (vv.y - mu) * rs * gv.y + bvv.y;
    ov.z = (vv.z - mu) * rs * gv.z + bvv.z;
    ov.w = (vv.w - mu) * rs * gv.w + bvv.w;
    ((float4*)(out + (long)t * DD))[tid] = ov;
}

__global__ void __launch_bounds__(256) ln_k(const float* __restrict__ x,
                                            const float* __restrict__ res,
                                            const float* __restrict__ gg,
                                            const float* __restrict__ bb,
                                            float* __restrict__ out)
{
    int t = blockIdx.x, tid = threadIdx.x;
    float4 vv = ((const float4*)(x + (long)t * DD))[tid];
    if (res) {
        float4 rr = ((const float4*)(res + (long)t * DD))[tid];
        vv.x += rr.x; vv.y += rr.y; vv.z += rr.z; vv.w += rr.w;
    }
    ln_body(vv, gg, bb, out, t, tid);
}

// ---------------- MoE combine + final LN ----------------
__global__ void __launch_bounds__(256) comb_ln_k(const float* __restrict__ sel,
                                                 const float* __restrict__ w2,
                                                 const float* __restrict__ gg,
                                                 const float* __restrict__ bb,
                                                 float* __restrict__ out)
{
    int t = blockIdx.x, tid = threadIdx.x;
    float w0 = w2[2 * t], w1 = w2[2 * t + 1];
    float4 va = ((const float4*)(sel + (long)(2 * t) * DD))[tid];
    float4 vb = ((const float4*)(sel + (long)(2 * t + 1) * DD))[tid];
    float4 vv;
    vv.x = w0 * va.x + w1 * vb.x;
    vv.y = w0 * va.y + w1 * vb.y;
    vv.z = w0 * va.z + w1 * vb.z;
    vv.w = w0 * va.w + w1 * vb.w;
    ln_body(vv, gg, bb, out, t, tid);
}

// ---------------- gate: logits, top-2 (jax tie semantics), softmax, routing ----------------
__global__ void zero_cnt_k(int* __restrict__ cnt) {
    if (threadIdx.x < NE) cnt[threadIdx.x] = 0;
}

__global__ void __launch_bounds__(256) gate_k(const float* __restrict__ x,
                                              const float* __restrict__ gW,
                                              const float* __restrict__ gb,
                                              float* __restrict__ w2,
                                              int* __restrict__ tok,
                                              int* __restrict__ slot,
                                              int* __restrict__ cnt)
{
    __shared__ float xs[DD];
    __shared__ float lg[NE];
    int t = blockIdx.x, tid = threadIdx.x;
    ((float4*)xs)[tid] = ((const float4*)(x + (long)t * DD))[tid];
    __syncthreads();
    int w = tid >> 5, lane = tid & 31;
    float s = 0.f;
    for (int d = lane; d < DD; d += 32) s += xs[d] * gW[(long)d * NE + w];
#pragma unroll
    for (int off = 16; off; off >>= 1) s += __shfl_down_sync(0xffffffffu, s, off);
    if (lane == 0) lg[w] = s + gb[w];
    __syncthreads();
    if (tid == 0) {
        float b1v = -1e30f; int i1 = 0;
        for (int e = 0; e < NE; e++) if (lg[e] > b1v) { b1v = lg[e]; i1 = e; }
        float b2v = -1e30f; int i2 = 0;
        for (int e = 0; e < NE; e++) if (e != i1 && lg[e] > b2v) { b2v = lg[e]; i2 = e; }
        float m = fmaxf(b1v, b2v);
        float e0 = expf(b1v - m), e1 = expf(b2v - m);
        float inv = 1.f / (e0 + e1);
        w2[2 * t]     = e0 * inv;
        w2[2 * t + 1] = e1 * inv;
        int p0 = atomicAdd(&cnt[i1], 1);
        tok[i1 * TT + p0] = t; slot[i1 * TT + p0] = 2 * t;
        int p1 = atomicAdd(&cnt[i2], 1);
        tok[i2 * TT + p1] = t; slot[i2 * TT + p1] = 2 * t + 1;
    }
}

// ---------------- host orchestration ----------------
extern "C" void kernel_launch(void* const* d_in, const int* in_sizes, int n_in,
                              void* d_out, int out_size) {
    const int*   src    = (const int*)  d_in[0];
    const float* emb    = (const float*)d_in[1];
    const float* Wq     = (const float*)d_in[2];
    const float* bq     = (const float*)d_in[3];
    const float* Wk     = (const float*)d_in[4];
    const float* bk     = (const float*)d_in[5];
    const float* Wv     = (const float*)d_in[6];
    const float* bv     = (const float*)d_in[7];
    const float* Wo     = (const float*)d_in[8];
    const float* bo     = (const float*)d_in[9];
    const float* ln1_g  = (const float*)d_in[10];
    const float* ln1_b  = (const float*)d_in[11];
    const float* W1     = (const float*)d_in[12];
    const float* b1     = (const float*)d_in[13];
    const float* W2     = (const float*)d_in[14];
    const float* b2     = (const float*)d_in[15];
    const float* ln2_g  = (const float*)d_in[16];
    const float* ln2_b  = (const float*)d_in[17];
    const float* gate_W = (const float*)d_in[18];
    const float* gate_b = (const float*)d_in[19];
    const float* eW1    = (const float*)d_in[20];
    const float* eb1    = (const float*)d_in[21];
    const float* eW2    = (const float*)d_in[22];
    const float* eb2    = (const float*)d_in[23];
    const float* fln_g  = (const float*)d_in[24];
    const float* fln_b  = (const float*)d_in[25];
    const float* out_W  = (const float*)d_in[26];
    const float* out_b  = (const float*)d_in[27];
    float* outp = (float*)d_out;

    float *p_x, *p_q, *p_k, *p_v, *p_ao, *p_t, *p_ff, *p_eh, *p_sel, *p_w2, *p_xln;
    int *p_tok, *p_slot, *p_cnt;
    cudaGetSymbolAddress((void**)&p_x,   g_x);
    cudaGetSymbolAddress((void**)&p_q,   g_q);
    cudaGetSymbolAddress((void**)&p_k,   g_k);
    cudaGetSymbolAddress((void**)&p_v,   g_v);
    cudaGetSymbolAddress((void**)&p_ao,  g_ao);
    cudaGetSymbolAddress((void**)&p_t,   g_t);
    cudaGetSymbolAddress((void**)&p_ff,  g_ff);
    cudaGetSymbolAddress((void**)&p_eh,  g_eh);
    cudaGetSymbolAddress((void**)&p_sel, g_sel);
    cudaGetSymbolAddress((void**)&p_w2,  g_w2);
    cudaGetSymbolAddress((void**)&p_xln, g_xln);
    cudaGetSymbolAddress((void**)&p_tok, g_tok);
    cudaGetSymbolAddress((void**)&p_slot,g_slot);
    cudaGetSymbolAddress((void**)&p_cnt, g_cnt);

    dim3 blk(256);

    embed_k<<<TT, blk>>>(src, emb, p_x);

    for (int l = 0; l < NL; l++) {
        const float* wq = Wq + (long)l * DD * DD;
        const float* wk = Wk + (long)l * DD * DD;
        const float* wv = Wv + (long)l * DD * DD;
        const float* wo = Wo + (long)l * DD * DD;
        const float* w1 = W1 + (long)l * DD * FF;
        const float* w2m = W2 + (long)l * FF * DD;

        dim3 gD(DD / 128, TT / 128, 1);   // N=1024
        dim3 gF(FF / 128, TT / 128, 1);   // N=4096

        gemm_k<<<gD, blk>>>(p_x, DD, wq, DD, 0, bq + (long)l * DD, 0, p_q, DD,
                            TT, DD, DD, 0, 0, 0, 0, 0);
        gemm_k<<<gD, blk>>>(p_x, DD, wk, DD, 0, bk + (long)l * DD, 0, p_k, DD,
                            TT, DD, DD, 0, 0, 0, 0, 0);
        gemm_k<<<gD, blk>>>(p_x, DD, wv, DD, 0, bv + (long)l * DD, 0, p_v, DD,
                            TT, DD, DD, 0, 0, 0, 0, 0);

        attn_k<<<dim3(SS / 32, HH, 2), blk>>>(p_q, p_k, p_v, p_ao);

        gemm_k<<<gD, blk>>>(p_ao, DD, wo, DD, 0, bo + (long)l * DD, 0, p_t, DD,
                            TT, DD, DD, 0, 0, 0, 0, 0);

        ln_k<<<TT, blk>>>(p_t, p_x, ln1_g + (long)l * DD, ln1_b + (long)l * DD, p_x);

        gemm_k<<<gF, blk>>>(p_x, DD, w1, FF, 0, b1 + (long)l * FF, 0, p_ff, FF,
                            TT, FF, DD, 0, 0, 0, 0, 1);
        gemm_k<<<gD, blk>>>(p_ff, FF, w2m, DD, 0, b2 + (long)l * DD, 0, p_t, DD,
                            TT, DD, FF, 0, 0, 0, 0, 0);

        ln_k<<<TT, blk>>>(p_t, p_x, ln2_g + (long)l * DD, ln2_b + (long)l * DD, p_x);
    }

    // ---- MoE ----
    zero_cnt_k<<<1, 32>>>(p_cnt);
    gate_k<<<TT, blk>>>(p_x, gate_W, gate_b, p_w2, p_tok, p_slot, p_cnt);

    // expert FFN1: h = relu(gather(x) @ eW1[e] + eb1[e]) -> g_eh (rows = slots)
    gemm_k<<<dim3(FF / 128, TT / 128, NE), blk>>>(
        p_x, DD, eW1, FF, (long)DD * FF, eb1, FF, p_eh, FF,
        TT, FF, DD, p_tok, p_slot, TT, p_cnt, 1);
    // expert FFN2: y = gather(h) @ eW2[e] + eb2[e] -> g_sel (rows = slots)
    gemm_k<<<dim3(DD / 128, TT / 128, NE), blk>>>(
        p_eh, FF, eW2, DD, (long)FF * DD, eb2, DD, p_sel, DD,
        TT, DD, FF, p_slot, p_slot, TT, p_cnt, 0);

    comb_ln_k<<<TT, blk>>>(p_sel, p_w2, fln_g, fln_b, p_xln);

    // output projection: [2048,1024] @ [1024,32000]
    gemm_k<<<dim3(VV / 128, TT / 128, 1), blk>>>(
        p_xln, DD, out_W, VV, 0, out_b, 0, outp, VV,
        TT, VV, DD, 0, 0, 0, 0, 0);
}